// round 14
// baseline (speedup 1.0000x reference)
#include <cuda_runtime.h>
#include <math.h>
#include <stdint.h>

#define E_TOTAL   480000
#define NN        30000
#define NG        512
#define TBL       2048
#define RMAX      3.5f
#define INV_NN    0.2631578947368421f    // 1/3.8
#define INV_SQNN  0.5129891760425771f    // 1/sqrt(3.8)
#define EID_CAP   720000
#define TROW      161                    // padded T row stride (bank-conflict-free)

// ---------------- scratch ---------------------------------------------------
__device__ float g_sh [E_TOTAL*16];
__device__ float g_r  [E_TOTAL];
__device__ float g_x0 [NN*16];
__device__ float g_x1 [NN*160];
__device__ float g_T2 [NN*112];
__device__ float g_C1 [16*2560];     // [i][k*16+j] = cg1[k,i,j]/3.8
__device__ float g_C2 [128*112];     // [I][k*16+j] = cg2[k,I,j]*0.5/sqrt(3.8)
__device__ float g_tw1[TBL*160];
__device__ float g_tw2[TBL*8];
__device__ int   g_cnt[NN];
__device__ int   g_rowptr[NN+1];
__device__ int   g_wptr[NN];
__device__ int   g_eid[EID_CAP];

__device__ __forceinline__ void red4(float* p, float a, float b, float c, float d){
    asm volatile("red.global.add.v4.f32 [%0], {%1, %2, %3, %4};"
                 :: "l"(p), "f"(a), "f"(b), "f"(c), "f"(d) : "memory");
}

// ---------------- zero + C matrices (merged) --------------------------------
__global__ void zero_kernel(float* out, const float* __restrict__ cg1,
                            const float* __restrict__ cg2){
    int i = blockIdx.x*blockDim.x + threadIdx.x;
    int s = gridDim.x*blockDim.x;
    for (int k=i; k<NN*16;  k+=s) g_x0[k]=0.f;
    for (int k=i; k<NN*160; k+=s) g_x1[k]=0.f;
    for (int k=i; k<NG*7;   k+=s) out[k]=0.f;
    for (int k=i; k<NN;     k+=s) g_cnt[k]=0;
    for (int idx=i; idx<16*2560; idx+=s){
        int ii = idx/2560, p = idx%2560;
        int k = p>>4, j = p&15;
        g_C1[idx] = cg1[k*256 + ii*16 + j] * INV_NN;
    }
    for (int idx=i; idx<128*112; idx+=s){
        int I = idx/112, c = idx%112;
        int k = c/16, j = c%16;
        g_C2[idx] = cg2[k*2048 + I*16 + j] * (0.5f * INV_SQNN);
    }
}

// ---------------- radial embed ----------------------------------------------
__device__ __forceinline__ void radial3(float r, float* emb){
    const float C = 1.14136f * 7.389056098930650f;
    #pragma unroll
    for (int i=0;i<3;i++){
        float u = r - (0.5f + (float)i);
        float d = u*u - 1.0f;
        emb[i] = (d < 0.f) ? C * expf(1.0f/d) * 1.7320508075688772f : 0.f;
    }
}

// ---------------- MLP lookup tables -----------------------------------------
__global__ void build_table(const float* __restrict__ W1a, const float* __restrict__ W2a,
                            const float* __restrict__ W1b, const float* __restrict__ W2b){
    __shared__ float hs [16][256];
    __shared__ float h2s[16][256];
    int base = blockIdx.x*16;
    const float s1 = 0.5773502691896258f;
    for (int idx=threadIdx.x; idx<16*256; idx+=256){
        int el = idx>>8, c = idx&255;
        float r = (float)(base+el) * (RMAX/(float)(TBL-1));
        float emb[3]; radial3(r, emb);
        float a = (emb[0]*W1a[c] + emb[1]*W1a[256+c] + emb[2]*W1a[512+c]) * s1;
        hs [el][c] = fmaxf(a, 0.f);
        float b = (emb[0]*W1b[c] + emb[1]*W1b[256+c] + emb[2]*W1b[512+c]) * s1;
        h2s[el][c] = fmaxf(b, 0.f);
    }
    __syncthreads();
    for (int idx=threadIdx.x; idx<16*160; idx+=256){
        int el = idx/160, k = idx%160;
        float acc = 0.f;
        #pragma unroll 4
        for (int c=0;c<256;c++) acc += hs[el][c]*W2a[c*160+k];
        g_tw1[(base+el)*160+k] = acc * 0.0625f;
    }
    for (int idx=threadIdx.x; idx<16*7; idx+=256){
        int el = idx/7, k = idx%7;
        float acc = 0.f;
        #pragma unroll 4
        for (int c=0;c<256;c++) acc += h2s[el][c]*W2b[c*7+k];
        g_tw2[(base+el)*8+k] = acc * 0.0625f;
    }
}

// ---------------- per-edge geometry + LIVE src histogram --------------------
__global__ void edge_geom(const float* __restrict__ pos,
                          const int* __restrict__ esrc,
                          const int* __restrict__ edst){
    int e = blockIdx.x*blockDim.x + threadIdx.x;
    if (e >= E_TOTAL) return;
    int s = esrc[e], d = edst[e];
    float ex = pos[s*3+0]-pos[d*3+0];
    float ey = pos[s*3+1]-pos[d*3+1];
    float ez = pos[s*3+2]-pos[d*3+2];
    float r  = sqrtf(ex*ex+ey*ey+ez*ez);
    g_r[e] = r;
    if (r < RMAX) atomicAdd(&g_cnt[s], 1);     // cull dead edges from CSR
    float inv = 1.0f/fmaxf(r, 1e-9f);
    float x = ex*inv, y = ey*inv, z = ez*inv;
    float x2=x*x, y2=y*y, z2=z*z;
    const float s3   = 1.7320508075688772f;
    const float s15  = 3.8729833462074170f;
    const float s15h = 1.9364916731037085f;
    const float s5h  = 1.1180339887498949f;
    const float s358 = 2.0916500663351889f;
    const float s105 = 10.246950765959598f;
    const float s218 = 1.6201851746019651f;
    const float s7h  = 1.3228756555322954f;
    const float s105h= 5.1234753829797990f;
    float sh[16];
    sh[0]=1.f;
    sh[1]=s3*x;  sh[2]=s3*y;  sh[3]=s3*z;
    sh[4]=s15*x*y; sh[5]=s15*y*z; sh[6]=s5h*(3.f*z2-1.f); sh[7]=s15*x*z; sh[8]=s15h*(x2-y2);
    sh[9]=s358*y*(3.f*x2-y2); sh[10]=s105*x*y*z; sh[11]=s218*y*(5.f*z2-1.f);
    sh[12]=s7h*z*(5.f*z2-3.f); sh[13]=s218*x*(5.f*z2-1.f); sh[14]=s105h*z*(x2-y2);
    sh[15]=s358*x*(x2-y2);
    float4* o = (float4*)(g_sh + (size_t)e*16);
    o[0] = make_float4(sh[0], sh[1], sh[2], sh[3]);
    o[1] = make_float4(sh[4], sh[5], sh[6], sh[7]);
    o[2] = make_float4(sh[8], sh[9], sh[10],sh[11]);
    o[3] = make_float4(sh[12],sh[13],sh[14],sh[15]);
    float* xp = g_x0 + (size_t)d*16;
    red4(xp+0,  sh[0], sh[1], sh[2], sh[3]);
    red4(xp+4,  sh[4], sh[5], sh[6], sh[7]);
    red4(xp+8,  sh[8], sh[9], sh[10],sh[11]);
    red4(xp+12, sh[12],sh[13],sh[14],sh[15]);
}

// ---------------- padded-CSR prefix sum: coalesced smem staging -------------
__global__ void prefix_kernel(){
    extern __shared__ int sc[];              // NN ints
    __shared__ int wsum[32];
    int t = threadIdx.x;
    int lane = t & 31, wid = t >> 5;
    for (int idx=t; idx<NN; idx+=1024)
        sc[idx] = (g_cnt[idx]+7)&~7;
    __syncthreads();
    int n0 = t*30;
    int s = 0;
    #pragma unroll
    for (int i=0;i<30;i++){
        int n = n0+i;
        if (n < NN) s += sc[n];
    }
    int x = s;
    #pragma unroll
    for (int off=1; off<32; off<<=1){
        int v = __shfl_up_sync(0xffffffffu, x, off);
        if (lane >= off) x += v;
    }
    if (lane == 31) wsum[wid] = x;
    __syncthreads();
    if (wid == 0){
        int y = wsum[lane];
        #pragma unroll
        for (int off=1; off<32; off<<=1){
            int v = __shfl_up_sync(0xffffffffu, y, off);
            if (lane >= off) y += v;
        }
        wsum[lane] = y;
    }
    __syncthreads();
    int total = wsum[31];
    int run = x - s + (wid ? wsum[wid-1] : 0);
    #pragma unroll
    for (int i=0;i<30;i++){
        int n = n0+i;
        if (n < NN){
            int v = sc[n];
            sc[n] = run;
            run += v;
        }
    }
    __syncthreads();
    for (int idx=t; idx<NN; idx+=1024){
        int v = sc[idx];
        g_rowptr[idx] = v;
        g_wptr[idx]   = v;
    }
    if (t == 0) g_rowptr[NN] = total;
}

// ---------------- scatter (live only) + pad ---------------------------------
__global__ void scatter_kernel(const int* __restrict__ esrc){
    int e = blockIdx.x*blockDim.x + threadIdx.x;
    if (e >= E_TOTAL) return;
    if (g_r[e] >= RMAX) return;
    int pos = atomicAdd(&g_wptr[esrc[e]], 1);
    g_eid[pos] = e;
}
__global__ void pad_kernel(){
    int n = blockIdx.x*blockDim.x + threadIdx.x;
    if (n >= NN) return;
    int s = g_wptr[n], e = g_rowptr[n+1];
    for (int p=s; p<e; p++) g_eid[p] = -1;
}

// ---------------- conv1 fused: 4 nodes/block, 256 threads, 8 warps ----------
// Same smem tile / same epilogue as the 659us kernel; 2x warps to hide
// epilogue latency (40 warps/SM at 5 blocks/SM).
__global__ __launch_bounds__(256) void conv1_fused(const int* __restrict__ edst){
    __shared__ float T_s[4*16*TROW];
    __shared__ float4 wsh4[8][8][4];
    __shared__ int    wge [8][8];
    __shared__ float  x0s [64];
    __shared__ int    rps [5];
    int t = threadIdx.x, lane = t&31, w = t>>5;
    int n0 = blockIdx.x*4;
    if (t < 5)  rps[t] = g_rowptr[n0+t];
    if (t < 64) x0s[t] = g_x0[(size_t)n0*16 + t];
    __syncthreads();

    // ---- phase 1: T[v,k,j] = sum_i C1[i,k,j] * x0[v,i]  (256 thr, 10 pos ea)
    {
        float acc[10][4];
        #pragma unroll
        for (int u=0;u<10;u++)
            #pragma unroll
            for (int v=0;v<4;v++) acc[u][v]=0.f;
        #pragma unroll
        for (int i=0;i<16;i++){
            float xv0=x0s[i], xv1=x0s[16+i], xv2=x0s[32+i], xv3=x0s[48+i];
            #pragma unroll
            for (int u=0;u<10;u++){
                float c = g_C1[i*2560 + t + 256*u];
                acc[u][0] += c*xv0; acc[u][1] += c*xv1;
                acc[u][2] += c*xv2; acc[u][3] += c*xv3;
            }
        }
        #pragma unroll
        for (int u=0;u<10;u++){
            int p = t + 256*u;
            int j = p&15, k = p>>4;
            #pragma unroll
            for (int v=0;v<4;v++) T_s[v*16*TROW + j*TROW + k] = acc[u][v];
        }
    }
    __syncthreads();

    // ---- phase 2: warp = 8-edge tile of one node (8 warps share tiles)
    int tt = (rps[4]-rps[0]) >> 3;
    for (int g=w; g<tt; g+=8){
        int base8 = rps[0] + g*8;
        int v = (base8>=rps[1]) + (base8>=rps[2]) + (base8>=rps[3]);
        __syncwarp();
        {
            int row = lane>>2, comp = lane&3;
            int ge = g_eid[base8+row];
            float4 sv = make_float4(0.f,0.f,0.f,0.f);
            if (ge >= 0) sv = ((const float4*)g_sh)[(size_t)ge*4 + comp];
            wsh4[w][row][comp] = sv;
            if (lane < 8) wge[w][lane] = g_eid[base8+lane];
        }
        __syncwarp();
        float acc[8][5];
        #pragma unroll
        for (int e=0;e<8;e++)
            #pragma unroll
            for (int q=0;q<5;q++) acc[e][q]=0.f;
        const float* Tp = T_s + v*16*TROW;
        const float* ash = (const float*)&wsh4[w][0][0];
        #pragma unroll
        for (int j=0;j<16;j++){
            float b0 = Tp[j*TROW + lane];
            float b1 = Tp[j*TROW + lane + 32];
            float b2 = Tp[j*TROW + lane + 64];
            float b3 = Tp[j*TROW + lane + 96];
            float b4 = Tp[j*TROW + lane + 128];
            #pragma unroll
            for (int e=0;e<8;e++){
                float a = ash[e*16 + j];
                acc[e][0] += a*b0; acc[e][1] += a*b1; acc[e][2] += a*b2;
                acc[e][3] += a*b3; acc[e][4] += a*b4;
            }
        }
        // epilogue: *w1(r) fp32 lerp, scatter to x1[dst]
        #pragma unroll
        for (int e=0;e<8;e++){
            int ge = wge[w][e];
            if (ge < 0) continue;
            float r = g_r[ge];
            float tc = r * ((float)(TBL-1)/RMAX);
            int   i0 = (int)tc; if (i0 > TBL-2) i0 = TBL-2;
            float f  = tc - (float)i0;
            int   d  = edst[ge];
            const float* t0 = g_tw1 + (size_t)i0*160 + lane;
            float* xp = g_x1 + (size_t)d*160 + lane;
            #pragma unroll
            for (int q=0;q<5;q++){
                float lo = t0[q*32], hi = t0[q*32+160];
                atomicAdd(xp + q*32, acc[e][q]*(lo + f*(hi-lo)));
            }
        }
    }
}

// ---------------- gate + T2 --------------------------------------------------
__global__ __launch_bounds__(256) void gate_t2(){
    __shared__ float xgs[8][128];
    int t = threadIdx.x;
    int n0 = blockIdx.x*8;
    #pragma unroll
    for (int u=0;u<4;u++){
        int idx = t + 256*u;
        int v = idx>>7, c = idx&127;
        const float* x = g_x1 + (size_t)(n0+v)*160;
        float o;
        if (c < 16)      o = fmaxf(x[c], 0.f);
        else if (c < 32) o = fabsf(x[c]);
        else {
            int ii = c - 32;
            int vv = ii/3;
            float gv = x[32 + vv];
            bool ur = (vv < 8) || (vv >= 16 && vv < 24);
            gv = ur ? fmaxf(gv, 0.f) : tanhf(gv);
            o = gv * x[64 + ii];
        }
        xgs[v][c] = o;
    }
    __syncthreads();
    if (t < 224){
        int p = t%112, h = t/112;
        float a0=0.f,a1=0.f,a2=0.f,a3=0.f;
        #pragma unroll 4
        for (int I=0;I<128;I++){
            float c = g_C2[I*112 + p];
            a0 += c*xgs[h*4+0][I];
            a1 += c*xgs[h*4+1][I];
            a2 += c*xgs[h*4+2][I];
            a3 += c*xgs[h*4+3][I];
        }
        g_T2[(size_t)(n0+h*4+0)*112 + p] = a0;
        g_T2[(size_t)(n0+h*4+1)*112 + p] = a1;
        g_T2[(size_t)(n0+h*4+2)*112 + p] = a2;
        g_T2[(size_t)(n0+h*4+3)*112 + p] = a3;
    }
}

// ---------------- conv2 via src-CSR: warp per node, T2 row in smem ----------
__global__ __launch_bounds__(256) void conv2_csr(const int* __restrict__ edst,
                                                 const int* __restrict__ batch,
                                                 float* __restrict__ out){
    __shared__ float t2s[8][112];
    int t = threadIdx.x, lane = t&31, w = t>>5;
    int n = blockIdx.x*8 + w;
    if (n >= NN) return;
    for (int idx=lane; idx<112; idx+=32)
        t2s[w][idx] = g_T2[(size_t)n*112 + idx];
    int r0 = g_rowptr[n], r1 = g_rowptr[n+1];
    __syncwarp();
    int jl = lane&15, h = lane>>4;
    int nt = (r1 - r0) >> 1;                 // padded count is even
    for (int q=0; q<nt; q++){
        int p = r0 + 2*q + h;
        int ge = g_eid[p];
        bool ok = (ge >= 0);
        float shv = ok ? g_sh[(size_t)ge*16 + jl] : 0.f;
        float acc[7];
        #pragma unroll
        for (int k=0;k<7;k++) acc[k] = t2s[w][k*16 + jl]*shv;
        #pragma unroll
        for (int off=8; off>=1; off>>=1)
            #pragma unroll
            for (int k=0;k<7;k++)
                acc[k] += __shfl_down_sync(0xffffffffu, acc[k], off, 16);
        if (ok && jl == 0){
            float r = g_r[ge];
            float tc = r * ((float)(TBL-1)/RMAX);
            int   i0 = (int)tc; if (i0 > TBL-2) i0 = TBL-2;
            float f  = tc - (float)i0;
            const float* t0 = g_tw2 + (size_t)i0*8;
            int bg = batch[edst[ge]];
            #pragma unroll
            for (int k=0;k<7;k++){
                float lo = t0[k], hi = t0[k+8];
                atomicAdd(out + bg*7 + k, acc[k]*(lo + f*(hi-lo)));
            }
        }
    }
}

// ---------------- launch ----------------------------------------------------
extern "C" void kernel_launch(void* const* d_in, const int* in_sizes, int n_in,
                              void* d_out, int out_size){
    const float* pos  = (const float*)d_in[0];
    const float* W1a  = (const float*)d_in[1];
    const float* W2a  = (const float*)d_in[2];
    const float* cg1  = (const float*)d_in[3];
    const float* W1b  = (const float*)d_in[4];
    const float* W2b  = (const float*)d_in[5];
    const float* cg2  = (const float*)d_in[6];
    const int*   esrc = (const int*)d_in[7];
    const int*   edst = (const int*)d_in[8];
    const int*   batch= (const int*)d_in[9];
    float* out = (float*)d_out;

    const int PREF_SMEM = NN*4;   // 120000 B
    cudaFuncSetAttribute(prefix_kernel, cudaFuncAttributeMaxDynamicSharedMemorySize, PREF_SMEM);

    zero_kernel   <<<2048, 256>>>(out, cg1, cg2);
    build_table   <<<TBL/16, 256>>>(W1a, W2a, W1b, W2b);
    edge_geom     <<<E_TOTAL/256, 256>>>(pos, esrc, edst);
    prefix_kernel <<<1, 1024, PREF_SMEM>>>();
    scatter_kernel<<<E_TOTAL/256, 256>>>(esrc);
    pad_kernel    <<<(NN+255)/256, 256>>>();
    conv1_fused   <<<NN/4, 256>>>(edst);
    gate_t2       <<<NN/8, 256>>>();
    conv2_csr     <<<(NN+7)/8, 256>>>(edst, batch, out);
}

// round 15
// speedup vs baseline: 1.2630x; 1.2630x over previous
#include <cuda_runtime.h>
#include <math.h>
#include <stdint.h>

#define E_TOTAL   480000
#define NN        30000
#define NG        512
#define TBL       2048
#define RMAX      3.5f
#define INV_NN    0.2631578947368421f    // 1/3.8
#define INV_SQNN  0.5129891760425771f    // 1/sqrt(3.8)
#define EID_CAP   720000
#define TROW      161                    // padded T row stride (bank-conflict-free)

// ---------------- scratch ---------------------------------------------------
__device__ float g_sh [E_TOTAL*16];
__device__ float g_r  [E_TOTAL];
__device__ float g_x0 [NN*16];
__device__ float g_x1 [NN*160];
__device__ float g_T2 [NN*112];
__device__ float g_C1 [16*2560];     // [i][k*16+j] = cg1[k,i,j]/3.8
__device__ float g_C2 [128*112];     // [I][k*16+j] = cg2[k,I,j]*0.5/sqrt(3.8)
__device__ float g_tw1[TBL*160];
__device__ float g_tw2[TBL*8];
__device__ int   g_cnt[NN];
__device__ int   g_rowptr[NN+1];
__device__ int   g_wptr[NN];
__device__ int   g_eid[EID_CAP];

__device__ __forceinline__ void red4(float* p, float a, float b, float c, float d){
    asm volatile("red.global.add.v4.f32 [%0], {%1, %2, %3, %4};"
                 :: "l"(p), "f"(a), "f"(b), "f"(c), "f"(d) : "memory");
}

// ---------------- zero + C matrices (merged) --------------------------------
__global__ void zero_kernel(float* out, const float* __restrict__ cg1,
                            const float* __restrict__ cg2){
    int i = blockIdx.x*blockDim.x + threadIdx.x;
    int s = gridDim.x*blockDim.x;
    for (int k=i; k<NN*16;  k+=s) g_x0[k]=0.f;
    for (int k=i; k<NN*160; k+=s) g_x1[k]=0.f;
    for (int k=i; k<NG*7;   k+=s) out[k]=0.f;
    for (int k=i; k<NN;     k+=s) g_cnt[k]=0;
    for (int idx=i; idx<16*2560; idx+=s){
        int ii = idx/2560, p = idx%2560;
        int k = p>>4, j = p&15;
        g_C1[idx] = cg1[k*256 + ii*16 + j] * INV_NN;
    }
    for (int idx=i; idx<128*112; idx+=s){
        int I = idx/112, c = idx%112;
        int k = c/16, j = c%16;
        g_C2[idx] = cg2[k*2048 + I*16 + j] * (0.5f * INV_SQNN);
    }
}

// ---------------- radial embed ----------------------------------------------
__device__ __forceinline__ void radial3(float r, float* emb){
    const float C = 1.14136f * 7.389056098930650f;
    #pragma unroll
    for (int i=0;i<3;i++){
        float u = r - (0.5f + (float)i);
        float d = u*u - 1.0f;
        emb[i] = (d < 0.f) ? C * expf(1.0f/d) * 1.7320508075688772f : 0.f;
    }
}

// ---------------- MLP lookup tables -----------------------------------------
__global__ void build_table(const float* __restrict__ W1a, const float* __restrict__ W2a,
                            const float* __restrict__ W1b, const float* __restrict__ W2b){
    __shared__ float hs [16][256];
    __shared__ float h2s[16][256];
    int base = blockIdx.x*16;
    const float s1 = 0.5773502691896258f;
    for (int idx=threadIdx.x; idx<16*256; idx+=256){
        int el = idx>>8, c = idx&255;
        float r = (float)(base+el) * (RMAX/(float)(TBL-1));
        float emb[3]; radial3(r, emb);
        float a = (emb[0]*W1a[c] + emb[1]*W1a[256+c] + emb[2]*W1a[512+c]) * s1;
        hs [el][c] = fmaxf(a, 0.f);
        float b = (emb[0]*W1b[c] + emb[1]*W1b[256+c] + emb[2]*W1b[512+c]) * s1;
        h2s[el][c] = fmaxf(b, 0.f);
    }
    __syncthreads();
    for (int idx=threadIdx.x; idx<16*160; idx+=256){
        int el = idx/160, k = idx%160;
        float acc = 0.f;
        #pragma unroll 4
        for (int c=0;c<256;c++) acc += hs[el][c]*W2a[c*160+k];
        g_tw1[(base+el)*160+k] = acc * 0.0625f;
    }
    for (int idx=threadIdx.x; idx<16*7; idx+=256){
        int el = idx/7, k = idx%7;
        float acc = 0.f;
        #pragma unroll 4
        for (int c=0;c<256;c++) acc += h2s[el][c]*W2b[c*7+k];
        g_tw2[(base+el)*8+k] = acc * 0.0625f;
    }
}

// ---------------- per-edge geometry + LIVE src histogram --------------------
__global__ void edge_geom(const float* __restrict__ pos,
                          const int* __restrict__ esrc,
                          const int* __restrict__ edst){
    int e = blockIdx.x*blockDim.x + threadIdx.x;
    if (e >= E_TOTAL) return;
    int s = esrc[e], d = edst[e];
    float ex = pos[s*3+0]-pos[d*3+0];
    float ey = pos[s*3+1]-pos[d*3+1];
    float ez = pos[s*3+2]-pos[d*3+2];
    float r  = sqrtf(ex*ex+ey*ey+ez*ez);
    g_r[e] = r;
    if (r < RMAX) atomicAdd(&g_cnt[s], 1);     // cull dead edges from CSR
    float inv = 1.0f/fmaxf(r, 1e-9f);
    float x = ex*inv, y = ey*inv, z = ez*inv;
    float x2=x*x, y2=y*y, z2=z*z;
    const float s3   = 1.7320508075688772f;
    const float s15  = 3.8729833462074170f;
    const float s15h = 1.9364916731037085f;
    const float s5h  = 1.1180339887498949f;
    const float s358 = 2.0916500663351889f;
    const float s105 = 10.246950765959598f;
    const float s218 = 1.6201851746019651f;
    const float s7h  = 1.3228756555322954f;
    const float s105h= 5.1234753829797990f;
    float sh[16];
    sh[0]=1.f;
    sh[1]=s3*x;  sh[2]=s3*y;  sh[3]=s3*z;
    sh[4]=s15*x*y; sh[5]=s15*y*z; sh[6]=s5h*(3.f*z2-1.f); sh[7]=s15*x*z; sh[8]=s15h*(x2-y2);
    sh[9]=s358*y*(3.f*x2-y2); sh[10]=s105*x*y*z; sh[11]=s218*y*(5.f*z2-1.f);
    sh[12]=s7h*z*(5.f*z2-3.f); sh[13]=s218*x*(5.f*z2-1.f); sh[14]=s105h*z*(x2-y2);
    sh[15]=s358*x*(x2-y2);
    float4* o = (float4*)(g_sh + (size_t)e*16);
    o[0] = make_float4(sh[0], sh[1], sh[2], sh[3]);
    o[1] = make_float4(sh[4], sh[5], sh[6], sh[7]);
    o[2] = make_float4(sh[8], sh[9], sh[10],sh[11]);
    o[3] = make_float4(sh[12],sh[13],sh[14],sh[15]);
    float* xp = g_x0 + (size_t)d*16;
    red4(xp+0,  sh[0], sh[1], sh[2], sh[3]);
    red4(xp+4,  sh[4], sh[5], sh[6], sh[7]);
    red4(xp+8,  sh[8], sh[9], sh[10],sh[11]);
    red4(xp+12, sh[12],sh[13],sh[14],sh[15]);
}

// ---------------- padded-CSR prefix sum: coalesced smem staging -------------
__global__ void prefix_kernel(){
    extern __shared__ int sc[];              // NN ints
    __shared__ int wsum[32];
    int t = threadIdx.x;
    int lane = t & 31, wid = t >> 5;
    for (int idx=t; idx<NN; idx+=1024)
        sc[idx] = (g_cnt[idx]+7)&~7;
    __syncthreads();
    int n0 = t*30;
    int s = 0;
    #pragma unroll
    for (int i=0;i<30;i++){
        int n = n0+i;
        if (n < NN) s += sc[n];
    }
    int x = s;
    #pragma unroll
    for (int off=1; off<32; off<<=1){
        int v = __shfl_up_sync(0xffffffffu, x, off);
        if (lane >= off) x += v;
    }
    if (lane == 31) wsum[wid] = x;
    __syncthreads();
    if (wid == 0){
        int y = wsum[lane];
        #pragma unroll
        for (int off=1; off<32; off<<=1){
            int v = __shfl_up_sync(0xffffffffu, y, off);
            if (lane >= off) y += v;
        }
        wsum[lane] = y;
    }
    __syncthreads();
    int total = wsum[31];
    int run = x - s + (wid ? wsum[wid-1] : 0);
    #pragma unroll
    for (int i=0;i<30;i++){
        int n = n0+i;
        if (n < NN){
            int v = sc[n];
            sc[n] = run;
            run += v;
        }
    }
    __syncthreads();
    for (int idx=t; idx<NN; idx+=1024){
        int v = sc[idx];
        g_rowptr[idx] = v;
        g_wptr[idx]   = v;
    }
    if (t == 0) g_rowptr[NN] = total;
}

// ---------------- scatter (live only) + pad ---------------------------------
__global__ void scatter_kernel(const int* __restrict__ esrc){
    int e = blockIdx.x*blockDim.x + threadIdx.x;
    if (e >= E_TOTAL) return;
    if (g_r[e] >= RMAX) return;
    int pos = atomicAdd(&g_wptr[esrc[e]], 1);
    g_eid[pos] = e;
}
__global__ void pad_kernel(){
    int n = blockIdx.x*blockDim.x + threadIdx.x;
    if (n >= NN) return;
    int s = g_wptr[n], e = g_rowptr[n+1];
    for (int p=s; p<e; p++) g_eid[p] = -1;
}

// ---------------- conv1 fused: 4 nodes/block, 128 threads -------------------
// Streaming operands (eid/sh/r/tables) use __ldcg (L2-only) so the 163KB C1
// matrix stays resident in L1 across tiles; C1 loads use the default L1 path.
__global__ __launch_bounds__(128) void conv1_fused(const int* __restrict__ edst){
    __shared__ float T_s[4*16*TROW];
    __shared__ float4 wsh4[4][8][4];
    __shared__ int    wge [4][8];
    __shared__ float  x0s [64];
    __shared__ int    rps [5];
    int t = threadIdx.x, lane = t&31, w = t>>5;
    int n0 = blockIdx.x*4;
    if (t < 5)  rps[t] = g_rowptr[n0+t];
    if (t < 64) x0s[t] = __ldcg(&g_x0[(size_t)n0*16 + t]);
    __syncthreads();

    // ---- phase 1: T[v,k,j] = sum_i C1[i,k,j] * x0[v,i]   (C1 via L1)
    #pragma unroll
    for (int qc=0; qc<2; qc++){
        float acc[10][4];
        #pragma unroll
        for (int u=0;u<10;u++)
            #pragma unroll
            for (int v=0;v<4;v++) acc[u][v]=0.f;
        #pragma unroll
        for (int i=0;i<16;i++){
            float xv0=x0s[i], xv1=x0s[16+i], xv2=x0s[32+i], xv3=x0s[48+i];
            #pragma unroll
            for (int u=0;u<10;u++){
                float c = g_C1[i*2560 + t + 128*(qc*10+u)];
                acc[u][0] += c*xv0; acc[u][1] += c*xv1;
                acc[u][2] += c*xv2; acc[u][3] += c*xv3;
            }
        }
        #pragma unroll
        for (int u=0;u<10;u++){
            int p = t + 128*(qc*10+u);
            int j = p&15, k = p>>4;
            #pragma unroll
            for (int v=0;v<4;v++) T_s[v*16*TROW + j*TROW + k] = acc[u][v];
        }
    }
    __syncthreads();

    // ---- phase 2: warp = 8-edge tile of one node
    int tt = (rps[4]-rps[0]) >> 3;
    for (int g=w; g<tt; g+=4){
        int base8 = rps[0] + g*8;
        int v = (base8>=rps[1]) + (base8>=rps[2]) + (base8>=rps[3]);
        __syncwarp();
        {
            int row = lane>>2, comp = lane&3;
            int ge = __ldcg(&g_eid[base8+row]);
            float4 sv = make_float4(0.f,0.f,0.f,0.f);
            if (ge >= 0) sv = __ldcg(((const float4*)g_sh) + (size_t)ge*4 + comp);
            wsh4[w][row][comp] = sv;
            if (lane < 8) wge[w][lane] = __ldcg(&g_eid[base8+lane]);
        }
        __syncwarp();
        float acc[8][5];
        #pragma unroll
        for (int e=0;e<8;e++)
            #pragma unroll
            for (int q=0;q<5;q++) acc[e][q]=0.f;
        const float* Tp = T_s + v*16*TROW;
        const float* ash = (const float*)&wsh4[w][0][0];
        #pragma unroll
        for (int j=0;j<16;j++){
            float b0 = Tp[j*TROW + lane];
            float b1 = Tp[j*TROW + lane + 32];
            float b2 = Tp[j*TROW + lane + 64];
            float b3 = Tp[j*TROW + lane + 96];
            float b4 = Tp[j*TROW + lane + 128];
            #pragma unroll
            for (int e=0;e<8;e++){
                float a = ash[e*16 + j];
                acc[e][0] += a*b0; acc[e][1] += a*b1; acc[e][2] += a*b2;
                acc[e][3] += a*b3; acc[e][4] += a*b4;
            }
        }
        // epilogue: *w1(r) fp32 lerp (L2-only loads), scatter to x1[dst]
        #pragma unroll
        for (int e=0;e<8;e++){
            int ge = wge[w][e];
            if (ge < 0) continue;
            float r = __ldcg(&g_r[ge]);
            float tc = r * ((float)(TBL-1)/RMAX);
            int   i0 = (int)tc; if (i0 > TBL-2) i0 = TBL-2;
            float f  = tc - (float)i0;
            int   d  = __ldcg(&edst[ge]);
            const float* t0 = g_tw1 + (size_t)i0*160 + lane;
            float* xp = g_x1 + (size_t)d*160 + lane;
            #pragma unroll
            for (int q=0;q<5;q++){
                float lo = __ldcg(t0 + q*32), hi = __ldcg(t0 + q*32 + 160);
                atomicAdd(xp + q*32, acc[e][q]*(lo + f*(hi-lo)));
            }
        }
    }
}

// ---------------- gate + T2 --------------------------------------------------
__global__ __launch_bounds__(256) void gate_t2(){
    __shared__ float xgs[8][128];
    int t = threadIdx.x;
    int n0 = blockIdx.x*8;
    #pragma unroll
    for (int u=0;u<4;u++){
        int idx = t + 256*u;
        int v = idx>>7, c = idx&127;
        const float* x = g_x1 + (size_t)(n0+v)*160;
        float o;
        if (c < 16)      o = fmaxf(x[c], 0.f);
        else if (c < 32) o = fabsf(x[c]);
        else {
            int ii = c - 32;
            int vv = ii/3;
            float gv = x[32 + vv];
            bool ur = (vv < 8) || (vv >= 16 && vv < 24);
            gv = ur ? fmaxf(gv, 0.f) : tanhf(gv);
            o = gv * x[64 + ii];
        }
        xgs[v][c] = o;
    }
    __syncthreads();
    if (t < 224){
        int p = t%112, h = t/112;
        float a0=0.f,a1=0.f,a2=0.f,a3=0.f;
        #pragma unroll 4
        for (int I=0;I<128;I++){
            float c = g_C2[I*112 + p];
            a0 += c*xgs[h*4+0][I];
            a1 += c*xgs[h*4+1][I];
            a2 += c*xgs[h*4+2][I];
            a3 += c*xgs[h*4+3][I];
        }
        g_T2[(size_t)(n0+h*4+0)*112 + p] = a0;
        g_T2[(size_t)(n0+h*4+1)*112 + p] = a1;
        g_T2[(size_t)(n0+h*4+2)*112 + p] = a2;
        g_T2[(size_t)(n0+h*4+3)*112 + p] = a3;
    }
}

// ---------------- conv2 via src-CSR: warp per node, T2 row in smem ----------
__global__ __launch_bounds__(256) void conv2_csr(const int* __restrict__ edst,
                                                 const int* __restrict__ batch,
                                                 float* __restrict__ out){
    __shared__ float t2s[8][112];
    int t = threadIdx.x, lane = t&31, w = t>>5;
    int n = blockIdx.x*8 + w;
    if (n >= NN) return;
    for (int idx=lane; idx<112; idx+=32)
        t2s[w][idx] = g_T2[(size_t)n*112 + idx];
    int r0 = g_rowptr[n], r1 = g_rowptr[n+1];
    __syncwarp();
    int jl = lane&15, h = lane>>4;
    int nt = (r1 - r0) >> 1;                 // padded count is even
    for (int q=0; q<nt; q++){
        int p = r0 + 2*q + h;
        int ge = g_eid[p];
        bool ok = (ge >= 0);
        float shv = ok ? g_sh[(size_t)ge*16 + jl] : 0.f;
        float acc[7];
        #pragma unroll
        for (int k=0;k<7;k++) acc[k] = t2s[w][k*16 + jl]*shv;
        #pragma unroll
        for (int off=8; off>=1; off>>=1)
            #pragma unroll
            for (int k=0;k<7;k++)
                acc[k] += __shfl_down_sync(0xffffffffu, acc[k], off, 16);
        if (ok && jl == 0){
            float r = g_r[ge];
            float tc = r * ((float)(TBL-1)/RMAX);
            int   i0 = (int)tc; if (i0 > TBL-2) i0 = TBL-2;
            float f  = tc - (float)i0;
            const float* t0 = g_tw2 + (size_t)i0*8;
            int bg = batch[edst[ge]];
            #pragma unroll
            for (int k=0;k<7;k++){
                float lo = t0[k], hi = t0[k+8];
                atomicAdd(out + bg*7 + k, acc[k]*(lo + f*(hi-lo)));
            }
        }
    }
}

// ---------------- launch ----------------------------------------------------
extern "C" void kernel_launch(void* const* d_in, const int* in_sizes, int n_in,
                              void* d_out, int out_size){
    const float* pos  = (const float*)d_in[0];
    const float* W1a  = (const float*)d_in[1];
    const float* W2a  = (const float*)d_in[2];
    const float* cg1  = (const float*)d_in[3];
    const float* W1b  = (const float*)d_in[4];
    const float* W2b  = (const float*)d_in[5];
    const float* cg2  = (const float*)d_in[6];
    const int*   esrc = (const int*)d_in[7];
    const int*   edst = (const int*)d_in[8];
    const int*   batch= (const int*)d_in[9];
    float* out = (float*)d_out;

    const int PREF_SMEM = NN*4;   // 120000 B
    cudaFuncSetAttribute(prefix_kernel, cudaFuncAttributeMaxDynamicSharedMemorySize, PREF_SMEM);

    zero_kernel   <<<2048, 256>>>(out, cg1, cg2);
    build_table   <<<TBL/16, 256>>>(W1a, W2a, W1b, W2b);
    edge_geom     <<<E_TOTAL/256, 256>>>(pos, esrc, edst);
    prefix_kernel <<<1, 1024, PREF_SMEM>>>();
    scatter_kernel<<<E_TOTAL/256, 256>>>(esrc);
    pad_kernel    <<<(NN+255)/256, 256>>>();
    conv1_fused   <<<NN/4, 128>>>(edst);
    gate_t2       <<<NN/8, 256>>>();
    conv2_csr     <<<(NN+7)/8, 256>>>(edst, batch, out);
}